// round 15
// baseline (speedup 1.0000x reference)
#include <cuda_runtime.h>
#include <cuda_fp16.h>
#include <math.h>

#define N_NODES 50000
#define N_EDGES 600000
#define HID 128
#define N_GRAPHS 64
#define CAP 64   // per-node slot capacity; Poisson(12) max deg ~34, P(overflow)~0

// ---------------- scratch ----------------
__device__ __half g_hh[N_NODES * HID];    // fp16 gather payload (pre-agg h)
__device__ __half g_acth[N_NODES * HID];  // fp16 layer activation (GEMM input / pool input)
__device__ float g_as[N_NODES];
__device__ float g_ad[N_NODES];
__device__ int   g_deg[N_NODES];
__device__ int   g_slot[N_NODES * CAP];   // slotted adjacency (real edges only)
// pre-built W fragments per layer: [layer(3)][ks(8)][npair(8)][lane(32)]
__device__ uint4 g_wfh[3 * 8 * 8 * 32];
__device__ uint4 g_wfl[3 * 8 * 8 * 32];

// ---------------- single-pass slotted scatter (replaces count/scan/fill) ----------------
__global__ void k_scatter(const int* __restrict__ ei) {
    int e = blockIdx.x * blockDim.x + threadIdx.x;
    if (e < N_EDGES) {
        int src = ei[e];
        int dst = ei[N_EDGES + e];
        int pos = atomicAdd(&g_deg[dst], 1);
        if (pos < CAP) g_slot[dst * CAP + pos] = src;
    }
}

// ---------------- MMA / ldmatrix helpers ----------------
__device__ __forceinline__ void mma_f16(float* c, const unsigned* a, unsigned b0, unsigned b1) {
    asm volatile(
        "mma.sync.aligned.m16n8k16.row.col.f32.f16.f16.f32 "
        "{%0,%1,%2,%3}, {%4,%5,%6,%7}, {%8,%9}, {%0,%1,%2,%3};"
        : "+f"(c[0]), "+f"(c[1]), "+f"(c[2]), "+f"(c[3])
        : "r"(a[0]), "r"(a[1]), "r"(a[2]), "r"(a[3]), "r"(b0), "r"(b1));
}

__device__ __forceinline__ void ldsm_x4(unsigned* r, unsigned addr) {
    asm volatile("ldmatrix.sync.aligned.m8n8.x4.shared.b16 {%0,%1,%2,%3}, [%4];"
                 : "=r"(r[0]), "=r"(r[1]), "=r"(r[2]), "=r"(r[3]) : "r"(addr));
}

__device__ __forceinline__ void ldsm_x4_t(unsigned* r, unsigned addr) {
    asm volatile("ldmatrix.sync.aligned.m8n8.x4.trans.shared.b16 {%0,%1,%2,%3}, [%4];"
                 : "=r"(r[0]), "=r"(r[1]), "=r"(r[2]), "=r"(r[3]) : "r"(addr));
}

__device__ __forceinline__ unsigned smem_u32(const void* p) {
    return (unsigned)__cvta_generic_to_shared(p);
}

#define PAH 136
#define PWH 136

// ---------------- W fragment prep: all 3 layers in one launch (grid=3) ----------------
__global__ __launch_bounds__(256) void k_prepw(const float* __restrict__ W0,
                                               const float* __restrict__ W1,
                                               const float* __restrict__ W2) {
    extern __shared__ char smemraw[];
    __half* sWh = reinterpret_cast<__half*>(smemraw);     // [128][PWH]
    __half* sWl = sWh + 128 * PWH;

    const float* W = (blockIdx.x == 0) ? W0 : ((blockIdx.x == 1) ? W1 : W2);
    uint4* outh = g_wfh + blockIdx.x * 2048;
    uint4* outl = g_wfl + blockIdx.x * 2048;

    int tid = threadIdx.x;
    int lane = tid & 31;
    int wid = tid >> 5;   // n-pair handled by this warp (cols wid*16)

    for (int i = tid; i < 128 * 32; i += 256) {
        int k = i >> 5, cq = i & 31;
        float4 v = reinterpret_cast<const float4*>(W)[k * 32 + cq];
        __half2 h0 = __floats2half2_rn(v.x, v.y);
        __half2 h1 = __floats2half2_rn(v.z, v.w);
        float2 f0 = __half22float2(h0);
        float2 f1 = __half22float2(h1);
        __half2 l0 = __floats2half2_rn(v.x - f0.x, v.y - f0.y);
        __half2 l1 = __floats2half2_rn(v.z - f1.x, v.w - f1.y);
        int o = k * PWH + 4 * cq;
        *reinterpret_cast<__half2*>(&sWh[o])     = h0;
        *reinterpret_cast<__half2*>(&sWh[o + 2]) = h1;
        *reinterpret_cast<__half2*>(&sWl[o])     = l0;
        *reinterpret_cast<__half2*>(&sWl[o + 2]) = l1;
    }
    __syncthreads();

    int b_k = (lane & 7) + ((lane >> 3) & 1) * 8;
    int b_n = (lane >> 4) * 8;
    unsigned aH = smem_u32(&sWh[b_k * PWH + wid * 16 + b_n]);
    unsigned aL = smem_u32(&sWl[b_k * PWH + wid * 16 + b_n]);

    #pragma unroll
    for (int ks = 0; ks < 8; ks++) {
        unsigned h[4], l[4];
        unsigned dW = (unsigned)(ks * 16 * PWH * 2);
        ldsm_x4_t(h, aH + dW);
        ldsm_x4_t(l, aL + dW);
        outh[(ks * 8 + wid) * 32 + lane] = make_uint4(h[0], h[1], h[2], h[3]);
        outl[(ks * 8 + wid) * 32 + lane] = make_uint4(l[0], l[1], l[2], l[3]);
    }
}

// ---------------- GEMM: A fp16 (plain), W fp16 split; A via ldmatrix, B via LDG ----------------
__global__ __launch_bounds__(256, 3) void k_gemm(const float* __restrict__ X,
                                                 const float* __restrict__ a_src,
                                                 const float* __restrict__ a_dst,
                                                 int use_x, int layer) {
    extern __shared__ char smemraw[];
    __half* sAh = reinterpret_cast<__half*>(smemraw);     // [64][PAH]
    float* salpha = reinterpret_cast<float*>(sAh + 64 * PAH);  // [64][2]

    const uint4* wfh = g_wfh + layer * 2048;
    const uint4* wfl = g_wfl + layer * 2048;
    int tid = threadIdx.x;
    int lane = tid & 31;
    int wid = tid >> 5;
    int row0 = blockIdx.x * 64;

    int rg = wid & 1;
    int cg = wid >> 1;
    int wr = rg * 32;
    int nc0 = cg * 32;

    if (tid < 128) salpha[tid] = 0.f;

    if (use_x) {
        // fp32 input: convert at staging
        for (int i = tid; i < 64 * 32; i += 256) {
            int r = i >> 5, cq = i & 31;
            int grow = row0 + r;
            float4 v = make_float4(0.f, 0.f, 0.f, 0.f);
            if (grow < N_NODES)
                v = reinterpret_cast<const float4*>(X)[grow * 32 + cq];
            __half2 h0 = __floats2half2_rn(v.x, v.y);
            __half2 h1 = __floats2half2_rn(v.z, v.w);
            int o = r * PAH + 4 * cq;
            *reinterpret_cast<__half2*>(&sAh[o])     = h0;
            *reinterpret_cast<__half2*>(&sAh[o + 2]) = h1;
        }
    } else {
        // fp16 activation: pure copy (8B per thread-iter)
        for (int i = tid; i < 64 * 32; i += 256) {
            int r = i >> 5, cq = i & 31;
            int grow = row0 + r;
            uint2 v = make_uint2(0u, 0u);
            if (grow < N_NODES)
                v = reinterpret_cast<const uint2*>(g_acth)[grow * 32 + cq];
            *reinterpret_cast<uint2*>(&sAh[r * PAH + 4 * cq]) = v;
        }
    }
    __syncthreads();

    int qr = lane >> 2;
    int qc = lane & 3;

    int a_r = (lane & 7) + ((lane >> 3) & 1) * 8;
    int a_k = (lane >> 4) * 8;
    unsigned aAh0 = smem_u32(&sAh[(wr + a_r) * PAH + a_k]);
    unsigned aAh1 = smem_u32(&sAh[(wr + 16 + a_r) * PAH + a_k]);

    float c[2][4][4];
    #pragma unroll
    for (int f = 0; f < 2; f++)
        #pragma unroll
        for (int nt = 0; nt < 4; nt++) {
            c[f][nt][0] = 0.f; c[f][nt][1] = 0.f; c[f][nt][2] = 0.f; c[f][nt][3] = 0.f;
        }

    #pragma unroll
    for (int ks = 0; ks < 8; ks++) {
        unsigned ah[2][4];
        unsigned dA = (unsigned)(ks * 16 * 2);
        ldsm_x4(ah[0], aAh0 + dA);
        ldsm_x4(ah[1], aAh1 + dA);

        uint4 bh0 = __ldg(&wfh[(ks * 8 + 2 * cg + 0) * 32 + lane]);
        uint4 bh1 = __ldg(&wfh[(ks * 8 + 2 * cg + 1) * 32 + lane]);
        uint4 bl0 = __ldg(&wfl[(ks * 8 + 2 * cg + 0) * 32 + lane]);
        uint4 bl1 = __ldg(&wfl[(ks * 8 + 2 * cg + 1) * 32 + lane]);
        unsigned bhp[2][4] = {{bh0.x, bh0.y, bh0.z, bh0.w}, {bh1.x, bh1.y, bh1.z, bh1.w}};
        unsigned blp[2][4] = {{bl0.x, bl0.y, bl0.z, bl0.w}, {bl1.x, bl1.y, bl1.z, bl1.w}};

        #pragma unroll
        for (int nt = 0; nt < 4; nt++) {
            int p = nt >> 1;
            int ix = (nt & 1) * 2;
            unsigned b0h = bhp[p][ix], b1h = bhp[p][ix + 1];
            unsigned b0l = blp[p][ix], b1l = blp[p][ix + 1];
            #pragma unroll
            for (int f = 0; f < 2; f++) {
                mma_f16(c[f][nt], ah[f], b0h, b1h);   // A * W_hi
                mma_f16(c[f][nt], ah[f], b0l, b1l);   // A * W_lo
            }
        }
    }

    float als[4] = {0.f, 0.f, 0.f, 0.f};
    float ald[4] = {0.f, 0.f, 0.f, 0.f};
    __half2* hh2 = reinterpret_cast<__half2*>(g_hh);

    #pragma unroll
    for (int f = 0; f < 2; f++) {
        int r_lo = row0 + wr + f * 16 + qr;
        int r_hi = r_lo + 8;
        #pragma unroll
        for (int nt = 0; nt < 4; nt++) {
            int col0 = nc0 + nt * 8 + 2 * qc;
            float s0 = __ldg(&a_src[col0]), s1 = __ldg(&a_src[col0 + 1]);
            float d0 = __ldg(&a_dst[col0]), d1 = __ldg(&a_dst[col0 + 1]);
            float* cc = c[f][nt];
            als[f * 2 + 0] += cc[0] * s0 + cc[1] * s1;
            ald[f * 2 + 0] += cc[0] * d0 + cc[1] * d1;
            als[f * 2 + 1] += cc[2] * s0 + cc[3] * s1;
            ald[f * 2 + 1] += cc[2] * d0 + cc[3] * d1;
            if (r_lo < N_NODES)
                hh2[r_lo * 64 + (col0 >> 1)] = __floats2half2_rn(cc[0], cc[1]);
            if (r_hi < N_NODES)
                hh2[r_hi * 64 + (col0 >> 1)] = __floats2half2_rn(cc[2], cc[3]);
        }
    }
    #pragma unroll
    for (int j = 0; j < 4; j++) {
        als[j] += __shfl_xor_sync(0xffffffffu, als[j], 1);
        als[j] += __shfl_xor_sync(0xffffffffu, als[j], 2);
        ald[j] += __shfl_xor_sync(0xffffffffu, ald[j], 1);
        ald[j] += __shfl_xor_sync(0xffffffffu, ald[j], 2);
    }
    if (qc == 0) {
        #pragma unroll
        for (int f = 0; f < 2; f++) {
            int lr_lo = wr + f * 16 + qr;
            atomicAdd(&salpha[lr_lo * 2 + 0], als[f * 2 + 0]);
            atomicAdd(&salpha[lr_lo * 2 + 1], ald[f * 2 + 0]);
            atomicAdd(&salpha[(lr_lo + 8) * 2 + 0], als[f * 2 + 1]);
            atomicAdd(&salpha[(lr_lo + 8) * 2 + 1], ald[f * 2 + 1]);
        }
    }
    __syncthreads();
    if (tid < 64) {
        int grow = row0 + tid;
        if (grow < N_NODES) {
            g_as[grow] = salpha[tid * 2 + 0];
            g_ad[grow] = salpha[tid * 2 + 1];
        }
    }
}

// ---------------- aggregation: slotted edges + analytic self-loop, fp16 act output ----------------
__global__ __launch_bounds__(256) void k_agg(const float* __restrict__ bias) {
    int w = (blockIdx.x * blockDim.x + threadIdx.x) >> 5;
    int lane = threadIdx.x & 31;
    if (w >= N_NODES) return;

    int deg = g_deg[w];
    if (deg > CAP) deg = CAP;
    const int base = w * CAP;
    float ad = g_ad[w];
    const uint2* h2 = reinterpret_cast<const uint2*>(g_hh);

    // self-loop term (never stored in slots)
    float vs = g_as[w] + ad;
    vs = vs > 0.f ? vs : 0.2f * vs;
    float ws = __expf(vs);
    float sc = ws;
    uint2 rs = h2[w * 32 + lane];
    float2 sa = __half22float2(*reinterpret_cast<__half2*>(&rs.x));
    float2 sb = __half22float2(*reinterpret_cast<__half2*>(&rs.y));
    float4 acc = make_float4(ws * sa.x, ws * sa.y, ws * sb.x, ws * sb.y);

    int e = 0;
    #pragma unroll 1
    for (; e + 4 <= deg; e += 4) {
        int s0 = g_slot[base + e + 0], s1 = g_slot[base + e + 1];
        int s2 = g_slot[base + e + 2], s3 = g_slot[base + e + 3];
        float v0 = g_as[s0] + ad, v1 = g_as[s1] + ad, v2 = g_as[s2] + ad, v3 = g_as[s3] + ad;
        v0 = v0 > 0.f ? v0 : 0.2f * v0;
        v1 = v1 > 0.f ? v1 : 0.2f * v1;
        v2 = v2 > 0.f ? v2 : 0.2f * v2;
        v3 = v3 > 0.f ? v3 : 0.2f * v3;
        float w0 = __expf(v0), w1 = __expf(v1), w2 = __expf(v2), w3 = __expf(v3);
        sc += (w0 + w1) + (w2 + w3);
        uint2 r0 = h2[s0 * 32 + lane];
        uint2 r1 = h2[s1 * 32 + lane];
        uint2 r2 = h2[s2 * 32 + lane];
        uint2 r3 = h2[s3 * 32 + lane];
        float2 a0 = __half22float2(*reinterpret_cast<__half2*>(&r0.x));
        float2 b0 = __half22float2(*reinterpret_cast<__half2*>(&r0.y));
        float2 a1 = __half22float2(*reinterpret_cast<__half2*>(&r1.x));
        float2 b1 = __half22float2(*reinterpret_cast<__half2*>(&r1.y));
        float2 a2 = __half22float2(*reinterpret_cast<__half2*>(&r2.x));
        float2 b2 = __half22float2(*reinterpret_cast<__half2*>(&r2.y));
        float2 a3 = __half22float2(*reinterpret_cast<__half2*>(&r3.x));
        float2 b3 = __half22float2(*reinterpret_cast<__half2*>(&r3.y));
        acc.x += w0 * a0.x + w1 * a1.x + w2 * a2.x + w3 * a3.x;
        acc.y += w0 * a0.y + w1 * a1.y + w2 * a2.y + w3 * a3.y;
        acc.z += w0 * b0.x + w1 * b1.x + w2 * b2.x + w3 * b3.x;
        acc.w += w0 * b0.y + w1 * b1.y + w2 * b2.y + w3 * b3.y;
    }
    for (; e < deg; ++e) {
        int s = g_slot[base + e];
        float v = g_as[s] + ad;
        v = v > 0.f ? v : 0.2f * v;
        float wgt = __expf(v);
        sc += wgt;
        uint2 r0 = h2[s * 32 + lane];
        float2 a0 = __half22float2(*reinterpret_cast<__half2*>(&r0.x));
        float2 b0 = __half22float2(*reinterpret_cast<__half2*>(&r0.y));
        acc.x += wgt * a0.x;
        acc.y += wgt * a0.y;
        acc.z += wgt * b0.x;
        acc.w += wgt * b0.y;
    }

    float inv = 1.f / (sc + 1e-16f);
    float4 bb = reinterpret_cast<const float4*>(bias)[lane];
    acc.x = acc.x * inv + bb.x;
    acc.y = acc.y * inv + bb.y;
    acc.z = acc.z * inv + bb.z;
    acc.w = acc.w * inv + bb.w;
    acc.x = acc.x > 0.f ? acc.x : (__expf(acc.x) - 1.f);
    acc.y = acc.y > 0.f ? acc.y : (__expf(acc.y) - 1.f);
    acc.z = acc.z > 0.f ? acc.z : (__expf(acc.z) - 1.f);
    acc.w = acc.w > 0.f ? acc.w : (__expf(acc.w) - 1.f);

    __half2 o0 = __floats2half2_rn(acc.x, acc.y);
    __half2 o1 = __floats2half2_rn(acc.z, acc.w);
    uint2 ov;
    ov.x = *reinterpret_cast<unsigned*>(&o0);
    ov.y = *reinterpret_cast<unsigned*>(&o1);
    reinterpret_cast<uint2*>(g_acth)[w * 32 + lane] = ov;
}

// ---------------- global mean pool (fp16 input) ----------------
__global__ __launch_bounds__(512) void k_pool(const int* __restrict__ batch,
                                              float* __restrict__ out) {
    int g = blockIdx.x;
    int tid = threadIdx.x;
    int sub = tid >> 7;
    int d = tid & 127;

    int lo = 0, hi = N_NODES;
    while (lo < hi) { int mid = (lo + hi) >> 1; if (batch[mid] < g) lo = mid + 1; else hi = mid; }
    int start = lo;
    lo = 0; hi = N_NODES;
    while (lo < hi) { int mid = (lo + hi) >> 1; if (batch[mid] < g + 1) lo = mid + 1; else hi = mid; }
    int stop = lo;

    float s = 0.f;
    for (int i = start + sub; i < stop; i += 4)
        s += __half2float(g_acth[i * 128 + d]);

    __shared__ float sm[4][128];
    sm[sub][d] = s;
    __syncthreads();
    if (sub == 0) {
        float tot = sm[0][d] + sm[1][d] + sm[2][d] + sm[3][d];
        int cnt = stop - start;
        out[g * 128 + d] = tot / (float)(cnt > 0 ? cnt : 1);
    }
}

// ---------------- launch ----------------
extern "C" void kernel_launch(void* const* d_in, const int* in_sizes, int n_in,
                              void* d_out, int out_size) {
    const float* x     = (const float*)d_in[0];
    const int*   ei    = (const int*)d_in[1];
    const int*   batch = (const int*)d_in[2];
    const float* W[3]   = { (const float*)d_in[3], (const float*)d_in[7],  (const float*)d_in[11] };
    const float* asr[3] = { (const float*)d_in[4], (const float*)d_in[8],  (const float*)d_in[12] };
    const float* ads[3] = { (const float*)d_in[5], (const float*)d_in[9],  (const float*)d_in[13] };
    const float* bs[3]  = { (const float*)d_in[6], (const float*)d_in[10], (const float*)d_in[14] };
    float* out = (float*)d_out;

    const int gemm_smem = (64 * PAH) * 2 + 128 * 4;            // ~17.9 KB
    const int prep_smem = (2 * 128 * PWH) * 2;                 // ~69.6 KB
    cudaFuncSetAttribute(k_gemm, cudaFuncAttributeMaxDynamicSharedMemorySize, gemm_smem);
    cudaFuncSetAttribute(k_prepw, cudaFuncAttributeMaxDynamicSharedMemorySize, prep_smem);

    void* degp = nullptr;
    cudaGetSymbolAddress(&degp, g_deg);

    const int gemm_grid = (N_NODES + 63) / 64;
    const int warp_grid = (N_NODES * 32 + 255) / 256;

    // fork: adjacency scatter on side stream, prepw+gemm1 on main stream
    cudaStream_t s2;
    cudaStreamCreateWithFlags(&s2, cudaStreamNonBlocking);
    cudaEvent_t evF, evJ;
    cudaEventCreateWithFlags(&evF, cudaEventDisableTiming);
    cudaEventCreateWithFlags(&evJ, cudaEventDisableTiming);

    cudaEventRecord(evF, 0);
    cudaStreamWaitEvent(s2, evF, 0);

    // side stream: memset + single-pass scatter (~15 us, fully hidden)
    cudaMemsetAsync(degp, 0, N_NODES * sizeof(int), s2);
    k_scatter<<<(N_EDGES + 255) / 256, 256, 0, s2>>>(ei);
    cudaEventRecord(evJ, s2);

    // main stream: W prep (all layers) + layer-1 GEMM (independent of adjacency)
    k_prepw<<<3, 256, prep_smem>>>(W[0], W[1], W[2]);
    k_gemm<<<gemm_grid, 256, gemm_smem>>>(x, asr[0], ads[0], 1, 0);

    // join: agg needs both gemm1 (main) and scatter (side)
    cudaStreamWaitEvent(0, evJ, 0);
    k_agg<<<warp_grid, 256>>>(bs[0]);

    for (int l = 1; l < 3; l++) {
        k_gemm<<<gemm_grid, 256, gemm_smem>>>(x, asr[l], ads[l], 0, l);
        k_agg<<<warp_grid, 256>>>(bs[l]);
    }

    k_pool<<<N_GRAPHS, 512>>>(batch, out);
}

// round 16
// speedup vs baseline: 1.0411x; 1.0411x over previous
#include <cuda_runtime.h>
#include <cuda_fp16.h>
#include <math.h>

#define N_NODES 50000
#define N_EDGES 600000
#define E_TOTAL (N_EDGES + N_NODES)
#define HID 128
#define N_GRAPHS 64
#define SCAN_BLOCKS ((N_NODES + 1023) / 1024)   // 49

// ---------------- scratch ----------------
__device__ __half g_hh[N_NODES * HID];    // fp16 gather payload (pre-agg h)
__device__ __half g_acth[N_NODES * HID];  // fp16 layer activation
__device__ float g_as[N_NODES];
__device__ float g_ad[N_NODES];
__device__ int   g_deg[N_NODES];
__device__ int   g_rowptr[N_NODES + 1];
__device__ int   g_cursor[N_NODES];
__device__ int   g_col[E_TOTAL];
__device__ int   g_bsum[64];
// pre-built W fragments per layer: [layer(3)][ks(8)][npair(8)][lane(32)]
__device__ uint4 g_wfh[3 * 8 * 8 * 32];
__device__ uint4 g_wfl[3 * 8 * 8 * 32];

// ---------------- CSR build (scalar, round-11/13 proven) ----------------
__global__ void k_count(const int* __restrict__ ei) {
    int e = blockIdx.x * blockDim.x + threadIdx.x;
    if (e < N_EDGES) atomicAdd(&g_deg[ei[N_EDGES + e]], 1);
}

__global__ __launch_bounds__(1024) void k_scan1() {
    __shared__ int wsum[32];
    int tid = threadIdx.x;
    int lane = tid & 31;
    int wid = tid >> 5;
    int i = blockIdx.x * 1024 + tid;
    int v = (i < N_NODES) ? (g_deg[i] + 1) : 0;   // +1 self-loop
    int x = v;
    #pragma unroll
    for (int off = 1; off < 32; off <<= 1) {
        int t = __shfl_up_sync(0xffffffffu, x, off);
        if (lane >= off) x += t;
    }
    if (lane == 31) wsum[wid] = x;
    __syncthreads();
    if (wid == 0) {
        int y = wsum[lane];
        #pragma unroll
        for (int off = 1; off < 32; off <<= 1) {
            int t = __shfl_up_sync(0xffffffffu, y, off);
            if (lane >= off) y += t;
        }
        wsum[lane] = y;
    }
    __syncthreads();
    int incl = x + (wid ? wsum[wid - 1] : 0);
    if (i < N_NODES) g_rowptr[i + 1] = incl;
    if (tid == 1023) g_bsum[blockIdx.x] = incl;
}

__global__ __launch_bounds__(256) void k_scan3() {
    __shared__ int s_off;
    int tid = threadIdx.x;
    int g = blockIdx.x >> 2;
    if (tid < 32) {
        int o = 0;
        for (int j = tid; j < g; j += 32) o += g_bsum[j];
        #pragma unroll
        for (int off = 16; off > 0; off >>= 1)
            o += __shfl_xor_sync(0xffffffffu, o, off);
        if (tid == 0) s_off = o;
    }
    __syncthreads();
    int i = blockIdx.x * 256 + tid;
    if (i == 0) g_rowptr[0] = 0;
    if (i < N_NODES) {
        int val = g_rowptr[i + 1] + s_off;
        g_rowptr[i + 1] = val;
        g_cursor[i] = val - (g_deg[i] + 1);
    }
}

__global__ void k_fill(const int* __restrict__ ei) {
    int idx = blockIdx.x * blockDim.x + threadIdx.x;
    if (idx < N_EDGES) {
        int src = ei[idx];
        int dst = ei[N_EDGES + idx];
        int pos = atomicAdd(&g_cursor[dst], 1);
        g_col[pos] = src;
    } else if (idx < E_TOTAL) {
        int node = idx - N_EDGES;
        int pos = atomicAdd(&g_cursor[node], 1);
        g_col[pos] = node;
    }
}

// ---------------- MMA / ldmatrix / packed-fp16 helpers ----------------
__device__ __forceinline__ void mma_f16(float* c, const unsigned* a, unsigned b0, unsigned b1) {
    asm volatile(
        "mma.sync.aligned.m16n8k16.row.col.f32.f16.f16.f32 "
        "{%0,%1,%2,%3}, {%4,%5,%6,%7}, {%8,%9}, {%0,%1,%2,%3};"
        : "+f"(c[0]), "+f"(c[1]), "+f"(c[2]), "+f"(c[3])
        : "r"(a[0]), "r"(a[1]), "r"(a[2]), "r"(a[3]), "r"(b0), "r"(b1));
}

__device__ __forceinline__ void ldsm_x4(unsigned* r, unsigned addr) {
    asm volatile("ldmatrix.sync.aligned.m8n8.x4.shared.b16 {%0,%1,%2,%3}, [%4];"
                 : "=r"(r[0]), "=r"(r[1]), "=r"(r[2]), "=r"(r[3]) : "r"(addr));
}

__device__ __forceinline__ void ldsm_x4_t(unsigned* r, unsigned addr) {
    asm volatile("ldmatrix.sync.aligned.m8n8.x4.trans.shared.b16 {%0,%1,%2,%3}, [%4];"
                 : "=r"(r[0]), "=r"(r[1]), "=r"(r[2]), "=r"(r[3]) : "r"(addr));
}

__device__ __forceinline__ unsigned smem_u32(const void* p) {
    return (unsigned)__cvta_generic_to_shared(p);
}

// packed fp16 fma: acc += a * b (2 halves per op)
__device__ __forceinline__ void hfma2(unsigned& acc, unsigned a, unsigned b) {
    asm("fma.rn.f16x2 %0, %1, %2, %0;" : "+r"(acc) : "r"(a), "r"(b));
}

#define PAH 136
#define PWH 136

// ---------------- W fragment prep: all 3 layers in one launch (grid=3) ----------------
__global__ __launch_bounds__(256) void k_prepw(const float* __restrict__ W0,
                                               const float* __restrict__ W1,
                                               const float* __restrict__ W2) {
    extern __shared__ char smemraw[];
    __half* sWh = reinterpret_cast<__half*>(smemraw);     // [128][PWH]
    __half* sWl = sWh + 128 * PWH;

    const float* W = (blockIdx.x == 0) ? W0 : ((blockIdx.x == 1) ? W1 : W2);
    uint4* outh = g_wfh + blockIdx.x * 2048;
    uint4* outl = g_wfl + blockIdx.x * 2048;

    int tid = threadIdx.x;
    int lane = tid & 31;
    int wid = tid >> 5;

    for (int i = tid; i < 128 * 32; i += 256) {
        int k = i >> 5, cq = i & 31;
        float4 v = reinterpret_cast<const float4*>(W)[k * 32 + cq];
        __half2 h0 = __floats2half2_rn(v.x, v.y);
        __half2 h1 = __floats2half2_rn(v.z, v.w);
        float2 f0 = __half22float2(h0);
        float2 f1 = __half22float2(h1);
        __half2 l0 = __floats2half2_rn(v.x - f0.x, v.y - f0.y);
        __half2 l1 = __floats2half2_rn(v.z - f1.x, v.w - f1.y);
        int o = k * PWH + 4 * cq;
        *reinterpret_cast<__half2*>(&sWh[o])     = h0;
        *reinterpret_cast<__half2*>(&sWh[o + 2]) = h1;
        *reinterpret_cast<__half2*>(&sWl[o])     = l0;
        *reinterpret_cast<__half2*>(&sWl[o + 2]) = l1;
    }
    __syncthreads();

    int b_k = (lane & 7) + ((lane >> 3) & 1) * 8;
    int b_n = (lane >> 4) * 8;
    unsigned aH = smem_u32(&sWh[b_k * PWH + wid * 16 + b_n]);
    unsigned aL = smem_u32(&sWl[b_k * PWH + wid * 16 + b_n]);

    #pragma unroll
    for (int ks = 0; ks < 8; ks++) {
        unsigned h[4], l[4];
        unsigned dW = (unsigned)(ks * 16 * PWH * 2);
        ldsm_x4_t(h, aH + dW);
        ldsm_x4_t(l, aL + dW);
        outh[(ks * 8 + wid) * 32 + lane] = make_uint4(h[0], h[1], h[2], h[3]);
        outl[(ks * 8 + wid) * 32 + lane] = make_uint4(l[0], l[1], l[2], l[3]);
    }
}

// ---------------- GEMM: A fp16 (plain), W fp16 split; A via ldmatrix, B via LDG ----------------
__global__ __launch_bounds__(256, 3) void k_gemm(const float* __restrict__ X,
                                                 const float* __restrict__ a_src,
                                                 const float* __restrict__ a_dst,
                                                 int use_x, int layer) {
    extern __shared__ char smemraw[];
    __half* sAh = reinterpret_cast<__half*>(smemraw);     // [64][PAH]
    float* salpha = reinterpret_cast<float*>(sAh + 64 * PAH);  // [64][2]

    const uint4* wfh = g_wfh + layer * 2048;
    const uint4* wfl = g_wfl + layer * 2048;
    int tid = threadIdx.x;
    int lane = tid & 31;
    int wid = tid >> 5;
    int row0 = blockIdx.x * 64;

    int rg = wid & 1;
    int cg = wid >> 1;
    int wr = rg * 32;
    int nc0 = cg * 32;

    if (tid < 128) salpha[tid] = 0.f;

    if (use_x) {
        for (int i = tid; i < 64 * 32; i += 256) {
            int r = i >> 5, cq = i & 31;
            int grow = row0 + r;
            float4 v = make_float4(0.f, 0.f, 0.f, 0.f);
            if (grow < N_NODES)
                v = reinterpret_cast<const float4*>(X)[grow * 32 + cq];
            __half2 h0 = __floats2half2_rn(v.x, v.y);
            __half2 h1 = __floats2half2_rn(v.z, v.w);
            int o = r * PAH + 4 * cq;
            *reinterpret_cast<__half2*>(&sAh[o])     = h0;
            *reinterpret_cast<__half2*>(&sAh[o + 2]) = h1;
        }
    } else {
        for (int i = tid; i < 64 * 32; i += 256) {
            int r = i >> 5, cq = i & 31;
            int grow = row0 + r;
            uint2 v = make_uint2(0u, 0u);
            if (grow < N_NODES)
                v = reinterpret_cast<const uint2*>(g_acth)[grow * 32 + cq];
            *reinterpret_cast<uint2*>(&sAh[r * PAH + 4 * cq]) = v;
        }
    }
    __syncthreads();

    int qr = lane >> 2;
    int qc = lane & 3;

    int a_r = (lane & 7) + ((lane >> 3) & 1) * 8;
    int a_k = (lane >> 4) * 8;
    unsigned aAh0 = smem_u32(&sAh[(wr + a_r) * PAH + a_k]);
    unsigned aAh1 = smem_u32(&sAh[(wr + 16 + a_r) * PAH + a_k]);

    float c[2][4][4];
    #pragma unroll
    for (int f = 0; f < 2; f++)
        #pragma unroll
        for (int nt = 0; nt < 4; nt++) {
            c[f][nt][0] = 0.f; c[f][nt][1] = 0.f; c[f][nt][2] = 0.f; c[f][nt][3] = 0.f;
        }

    #pragma unroll
    for (int ks = 0; ks < 8; ks++) {
        unsigned ah[2][4];
        unsigned dA = (unsigned)(ks * 16 * 2);
        ldsm_x4(ah[0], aAh0 + dA);
        ldsm_x4(ah[1], aAh1 + dA);

        uint4 bh0 = __ldg(&wfh[(ks * 8 + 2 * cg + 0) * 32 + lane]);
        uint4 bh1 = __ldg(&wfh[(ks * 8 + 2 * cg + 1) * 32 + lane]);
        uint4 bl0 = __ldg(&wfl[(ks * 8 + 2 * cg + 0) * 32 + lane]);
        uint4 bl1 = __ldg(&wfl[(ks * 8 + 2 * cg + 1) * 32 + lane]);
        unsigned bhp[2][4] = {{bh0.x, bh0.y, bh0.z, bh0.w}, {bh1.x, bh1.y, bh1.z, bh1.w}};
        unsigned blp[2][4] = {{bl0.x, bl0.y, bl0.z, bl0.w}, {bl1.x, bl1.y, bl1.z, bl1.w}};

        #pragma unroll
        for (int nt = 0; nt < 4; nt++) {
            int p = nt >> 1;
            int ix = (nt & 1) * 2;
            unsigned b0h = bhp[p][ix], b1h = bhp[p][ix + 1];
            unsigned b0l = blp[p][ix], b1l = blp[p][ix + 1];
            #pragma unroll
            for (int f = 0; f < 2; f++) {
                mma_f16(c[f][nt], ah[f], b0h, b1h);   // A * W_hi
                mma_f16(c[f][nt], ah[f], b0l, b1l);   // A * W_lo
            }
        }
    }

    float als[4] = {0.f, 0.f, 0.f, 0.f};
    float ald[4] = {0.f, 0.f, 0.f, 0.f};
    __half2* hh2 = reinterpret_cast<__half2*>(g_hh);

    #pragma unroll
    for (int f = 0; f < 2; f++) {
        int r_lo = row0 + wr + f * 16 + qr;
        int r_hi = r_lo + 8;
        #pragma unroll
        for (int nt = 0; nt < 4; nt++) {
            int col0 = nc0 + nt * 8 + 2 * qc;
            float s0 = __ldg(&a_src[col0]), s1 = __ldg(&a_src[col0 + 1]);
            float d0 = __ldg(&a_dst[col0]), d1 = __ldg(&a_dst[col0 + 1]);
            float* cc = c[f][nt];
            als[f * 2 + 0] += cc[0] * s0 + cc[1] * s1;
            ald[f * 2 + 0] += cc[0] * d0 + cc[1] * d1;
            als[f * 2 + 1] += cc[2] * s0 + cc[3] * s1;
            ald[f * 2 + 1] += cc[2] * d0 + cc[3] * d1;
            if (r_lo < N_NODES)
                hh2[r_lo * 64 + (col0 >> 1)] = __floats2half2_rn(cc[0], cc[1]);
            if (r_hi < N_NODES)
                hh2[r_hi * 64 + (col0 >> 1)] = __floats2half2_rn(cc[2], cc[3]);
        }
    }
    #pragma unroll
    for (int j = 0; j < 4; j++) {
        als[j] += __shfl_xor_sync(0xffffffffu, als[j], 1);
        als[j] += __shfl_xor_sync(0xffffffffu, als[j], 2);
        ald[j] += __shfl_xor_sync(0xffffffffu, ald[j], 1);
        ald[j] += __shfl_xor_sync(0xffffffffu, ald[j], 2);
    }
    if (qc == 0) {
        #pragma unroll
        for (int f = 0; f < 2; f++) {
            int lr_lo = wr + f * 16 + qr;
            atomicAdd(&salpha[lr_lo * 2 + 0], als[f * 2 + 0]);
            atomicAdd(&salpha[lr_lo * 2 + 1], ald[f * 2 + 0]);
            atomicAdd(&salpha[(lr_lo + 8) * 2 + 0], als[f * 2 + 1]);
            atomicAdd(&salpha[(lr_lo + 8) * 2 + 1], ald[f * 2 + 1]);
        }
    }
    __syncthreads();
    if (tid < 64) {
        int grow = row0 + tid;
        if (grow < N_NODES) {
            g_as[grow] = salpha[tid * 2 + 0];
            g_ad[grow] = salpha[tid * 2 + 1];
        }
    }
}

// ---------------- aggregation: single-pass softmax + packed HFMA2 accumulation ----------------
__global__ __launch_bounds__(256) void k_agg(const float* __restrict__ bias) {
    int w = (blockIdx.x * blockDim.x + threadIdx.x) >> 5;
    int lane = threadIdx.x & 31;
    if (w >= N_NODES) return;

    int beg = g_rowptr[w];
    int end = g_rowptr[w + 1];
    float ad = g_ad[w];

    unsigned acc0 = 0u, acc1 = 0u;   // half2 accumulators (dims 4l..4l+1, 4l+2..4l+3)
    float sc = 0.f;
    const uint2* h2 = reinterpret_cast<const uint2*>(g_hh);

    int e = beg;
    #pragma unroll 1
    for (; e + 4 <= end; e += 4) {
        int s0 = g_col[e + 0], s1 = g_col[e + 1], s2 = g_col[e + 2], s3 = g_col[e + 3];
        float v0 = g_as[s0] + ad, v1 = g_as[s1] + ad, v2 = g_as[s2] + ad, v3 = g_as[s3] + ad;
        v0 = v0 > 0.f ? v0 : 0.2f * v0;
        v1 = v1 > 0.f ? v1 : 0.2f * v1;
        v2 = v2 > 0.f ? v2 : 0.2f * v2;
        v3 = v3 > 0.f ? v3 : 0.2f * v3;
        float w0 = __expf(v0), w1 = __expf(v1), w2 = __expf(v2), w3 = __expf(v3);
        sc += (w0 + w1) + (w2 + w3);
        __half2 wh0 = __floats2half2_rn(w0, w0);
        __half2 wh1 = __floats2half2_rn(w1, w1);
        __half2 wh2 = __floats2half2_rn(w2, w2);
        __half2 wh3 = __floats2half2_rn(w3, w3);
        uint2 r0 = h2[s0 * 32 + lane];
        uint2 r1 = h2[s1 * 32 + lane];
        uint2 r2 = h2[s2 * 32 + lane];
        uint2 r3 = h2[s3 * 32 + lane];
        hfma2(acc0, r0.x, *reinterpret_cast<unsigned*>(&wh0));
        hfma2(acc1, r0.y, *reinterpret_cast<unsigned*>(&wh0));
        hfma2(acc0, r1.x, *reinterpret_cast<unsigned*>(&wh1));
        hfma2(acc1, r1.y, *reinterpret_cast<unsigned*>(&wh1));
        hfma2(acc0, r2.x, *reinterpret_cast<unsigned*>(&wh2));
        hfma2(acc1, r2.y, *reinterpret_cast<unsigned*>(&wh2));
        hfma2(acc0, r3.x, *reinterpret_cast<unsigned*>(&wh3));
        hfma2(acc1, r3.y, *reinterpret_cast<unsigned*>(&wh3));
    }
    for (; e < end; ++e) {
        int s = g_col[e];
        float v = g_as[s] + ad;
        v = v > 0.f ? v : 0.2f * v;
        float wgt = __expf(v);
        sc += wgt;
        __half2 wh = __floats2half2_rn(wgt, wgt);
        uint2 r0 = h2[s * 32 + lane];
        hfma2(acc0, r0.x, *reinterpret_cast<unsigned*>(&wh));
        hfma2(acc1, r0.y, *reinterpret_cast<unsigned*>(&wh));
    }

    float2 f0 = __half22float2(*reinterpret_cast<__half2*>(&acc0));
    float2 f1 = __half22float2(*reinterpret_cast<__half2*>(&acc1));
    float inv = 1.f / (sc + 1e-16f);
    float4 bb = reinterpret_cast<const float4*>(bias)[lane];
    float4 acc;
    acc.x = f0.x * inv + bb.x;
    acc.y = f0.y * inv + bb.y;
    acc.z = f1.x * inv + bb.z;
    acc.w = f1.y * inv + bb.w;
    acc.x = acc.x > 0.f ? acc.x : (__expf(acc.x) - 1.f);
    acc.y = acc.y > 0.f ? acc.y : (__expf(acc.y) - 1.f);
    acc.z = acc.z > 0.f ? acc.z : (__expf(acc.z) - 1.f);
    acc.w = acc.w > 0.f ? acc.w : (__expf(acc.w) - 1.f);

    __half2 o0 = __floats2half2_rn(acc.x, acc.y);
    __half2 o1 = __floats2half2_rn(acc.z, acc.w);
    uint2 ov;
    ov.x = *reinterpret_cast<unsigned*>(&o0);
    ov.y = *reinterpret_cast<unsigned*>(&o1);
    reinterpret_cast<uint2*>(g_acth)[w * 32 + lane] = ov;
}

// ---------------- global mean pool (fp16 input) ----------------
__global__ __launch_bounds__(512) void k_pool(const int* __restrict__ batch,
                                              float* __restrict__ out) {
    int g = blockIdx.x;
    int tid = threadIdx.x;
    int sub = tid >> 7;
    int d = tid & 127;

    int lo = 0, hi = N_NODES;
    while (lo < hi) { int mid = (lo + hi) >> 1; if (batch[mid] < g) lo = mid + 1; else hi = mid; }
    int start = lo;
    lo = 0; hi = N_NODES;
    while (lo < hi) { int mid = (lo + hi) >> 1; if (batch[mid] < g + 1) lo = mid + 1; else hi = mid; }
    int stop = lo;

    float s = 0.f;
    for (int i = start + sub; i < stop; i += 4)
        s += __half2float(g_acth[i * 128 + d]);

    __shared__ float sm[4][128];
    sm[sub][d] = s;
    __syncthreads();
    if (sub == 0) {
        float tot = sm[0][d] + sm[1][d] + sm[2][d] + sm[3][d];
        int cnt = stop - start;
        out[g * 128 + d] = tot / (float)(cnt > 0 ? cnt : 1);
    }
}

// ---------------- launch ----------------
extern "C" void kernel_launch(void* const* d_in, const int* in_sizes, int n_in,
                              void* d_out, int out_size) {
    const float* x     = (const float*)d_in[0];
    const int*   ei    = (const int*)d_in[1];
    const int*   batch = (const int*)d_in[2];
    const float* W[3]   = { (const float*)d_in[3], (const float*)d_in[7],  (const float*)d_in[11] };
    const float* asr[3] = { (const float*)d_in[4], (const float*)d_in[8],  (const float*)d_in[12] };
    const float* ads[3] = { (const float*)d_in[5], (const float*)d_in[9],  (const float*)d_in[13] };
    const float* bs[3]  = { (const float*)d_in[6], (const float*)d_in[10], (const float*)d_in[14] };
    float* out = (float*)d_out;

    const int gemm_smem = (64 * PAH) * 2 + 128 * 4;            // ~17.9 KB
    const int prep_smem = (2 * 128 * PWH) * 2;                 // ~69.6 KB
    cudaFuncSetAttribute(k_gemm, cudaFuncAttributeMaxDynamicSharedMemorySize, gemm_smem);
    cudaFuncSetAttribute(k_prepw, cudaFuncAttributeMaxDynamicSharedMemorySize, prep_smem);

    void* degp = nullptr;
    cudaGetSymbolAddress(&degp, g_deg);

    const int gemm_grid = (N_NODES + 63) / 64;
    const int warp_grid = (N_NODES * 32 + 255) / 256;

    // fork: CSR build on side stream, prepw+gemm1 on main stream
    cudaStream_t s2;
    cudaStreamCreateWithFlags(&s2, cudaStreamNonBlocking);
    cudaEvent_t evF, evJ;
    cudaEventCreateWithFlags(&evF, cudaEventDisableTiming);
    cudaEventCreateWithFlags(&evJ, cudaEventDisableTiming);

    cudaEventRecord(evF, 0);
    cudaStreamWaitEvent(s2, evF, 0);

    // side stream: CSR chain (scalar kernels — proven fastest)
    cudaMemsetAsync(degp, 0, N_NODES * sizeof(int), s2);
    k_count<<<(N_EDGES + 255) / 256, 256, 0, s2>>>(ei);
    k_scan1<<<SCAN_BLOCKS, 1024, 0, s2>>>();
    k_scan3<<<(N_NODES + 255) / 256, 256, 0, s2>>>();
    k_fill<<<(E_TOTAL + 255) / 256, 256, 0, s2>>>(ei);
    cudaEventRecord(evJ, s2);

    // main stream: W prep (all layers) + layer-1 GEMM (independent of CSR)
    k_prepw<<<3, 256, prep_smem>>>(W[0], W[1], W[2]);
    k_gemm<<<gemm_grid, 256, gemm_smem>>>(x, asr[0], ads[0], 1, 0);

    // join: agg needs both gemm1 (main) and fill (side)
    cudaStreamWaitEvent(0, evJ, 0);
    k_agg<<<warp_grid, 256>>>(bs[0]);

    for (int l = 1; l < 3; l++) {
        k_gemm<<<gemm_grid, 256, gemm_smem>>>(x, asr[l], ads[l], 0, l);
        k_agg<<<warp_grid, 256>>>(bs[l]);
    }

    k_pool<<<N_GRAPHS, 512>>>(batch, out);
}

// round 17
// speedup vs baseline: 1.1324x; 1.0877x over previous
#include <cuda_runtime.h>
#include <cuda_fp16.h>
#include <math.h>

#define N_NODES 50000
#define N_EDGES 600000
#define E_TOTAL (N_EDGES + N_NODES)
#define HID 128
#define N_GRAPHS 64
#define SCAN_BLOCKS ((N_NODES + 1023) / 1024)   // 49

// ---------------- scratch ----------------
__device__ __half g_hh[N_NODES * HID];    // fp16 gather payload (pre-agg h)
__device__ __half g_acth[N_NODES * HID];  // fp16 layer activation
__device__ float g_as[N_NODES];
__device__ float g_ad[N_NODES];
__device__ int   g_deg[N_NODES];
__device__ int   g_rowptr[N_NODES + 1];
__device__ int   g_cursor[N_NODES];
__device__ int   g_col[E_TOTAL];
__device__ int   g_bsum[64];
// pre-built W fragments per layer: [layer(3)][ks(8)][npair(8)][lane(32)]
__device__ uint4 g_wfh[3 * 8 * 8 * 32];
__device__ uint4 g_wfl[3 * 8 * 8 * 32];

// ---------------- CSR build (scalar, proven) ----------------
__global__ void k_count(const int* __restrict__ ei) {
    int e = blockIdx.x * blockDim.x + threadIdx.x;
    if (e < N_EDGES) atomicAdd(&g_deg[ei[N_EDGES + e]], 1);
}

__global__ __launch_bounds__(1024) void k_scan1() {
    __shared__ int wsum[32];
    int tid = threadIdx.x;
    int lane = tid & 31;
    int wid = tid >> 5;
    int i = blockIdx.x * 1024 + tid;
    int v = (i < N_NODES) ? (g_deg[i] + 1) : 0;   // +1 self-loop
    int x = v;
    #pragma unroll
    for (int off = 1; off < 32; off <<= 1) {
        int t = __shfl_up_sync(0xffffffffu, x, off);
        if (lane >= off) x += t;
    }
    if (lane == 31) wsum[wid] = x;
    __syncthreads();
    if (wid == 0) {
        int y = wsum[lane];
        #pragma unroll
        for (int off = 1; off < 32; off <<= 1) {
            int t = __shfl_up_sync(0xffffffffu, y, off);
            if (lane >= off) y += t;
        }
        wsum[lane] = y;
    }
    __syncthreads();
    int incl = x + (wid ? wsum[wid - 1] : 0);
    if (i < N_NODES) g_rowptr[i + 1] = incl;
    if (tid == 1023) g_bsum[blockIdx.x] = incl;
}

__global__ __launch_bounds__(256) void k_scan3() {
    __shared__ int s_off;
    int tid = threadIdx.x;
    int g = blockIdx.x >> 2;
    if (tid < 32) {
        int o = 0;
        for (int j = tid; j < g; j += 32) o += g_bsum[j];
        #pragma unroll
        for (int off = 16; off > 0; off >>= 1)
            o += __shfl_xor_sync(0xffffffffu, o, off);
        if (tid == 0) s_off = o;
    }
    __syncthreads();
    int i = blockIdx.x * 256 + tid;
    if (i == 0) g_rowptr[0] = 0;
    if (i < N_NODES) {
        int val = g_rowptr[i + 1] + s_off;
        g_rowptr[i + 1] = val;
        g_cursor[i] = val - (g_deg[i] + 1);
    }
}

__global__ void k_fill(const int* __restrict__ ei) {
    int idx = blockIdx.x * blockDim.x + threadIdx.x;
    if (idx < N_EDGES) {
        int src = ei[idx];
        int dst = ei[N_EDGES + idx];
        int pos = atomicAdd(&g_cursor[dst], 1);
        g_col[pos] = src;
    } else if (idx < E_TOTAL) {
        int node = idx - N_EDGES;
        int pos = atomicAdd(&g_cursor[node], 1);
        g_col[pos] = node;
    }
}

// ---------------- MMA / ldmatrix / packed-fp16 helpers ----------------
__device__ __forceinline__ void mma_f16(float* c, const unsigned* a, unsigned b0, unsigned b1) {
    asm volatile(
        "mma.sync.aligned.m16n8k16.row.col.f32.f16.f16.f32 "
        "{%0,%1,%2,%3}, {%4,%5,%6,%7}, {%8,%9}, {%0,%1,%2,%3};"
        : "+f"(c[0]), "+f"(c[1]), "+f"(c[2]), "+f"(c[3])
        : "r"(a[0]), "r"(a[1]), "r"(a[2]), "r"(a[3]), "r"(b0), "r"(b1));
}

__device__ __forceinline__ void ldsm_x4(unsigned* r, unsigned addr) {
    asm volatile("ldmatrix.sync.aligned.m8n8.x4.shared.b16 {%0,%1,%2,%3}, [%4];"
                 : "=r"(r[0]), "=r"(r[1]), "=r"(r[2]), "=r"(r[3]) : "r"(addr));
}

__device__ __forceinline__ void ldsm_x4_t(unsigned* r, unsigned addr) {
    asm volatile("ldmatrix.sync.aligned.m8n8.x4.trans.shared.b16 {%0,%1,%2,%3}, [%4];"
                 : "=r"(r[0]), "=r"(r[1]), "=r"(r[2]), "=r"(r[3]) : "r"(addr));
}

__device__ __forceinline__ unsigned smem_u32(const void* p) {
    return (unsigned)__cvta_generic_to_shared(p);
}

__device__ __forceinline__ void hfma2(unsigned& acc, unsigned a, unsigned b) {
    asm("fma.rn.f16x2 %0, %1, %2, %0;" : "+r"(acc) : "r"(a), "r"(b));
}

__device__ __forceinline__ unsigned hadd2u(unsigned a, unsigned b) {
    unsigned r;
    asm("add.rn.f16x2 %0, %1, %2;" : "=r"(r) : "r"(a), "r"(b));
    return r;
}

#define PAH 136
#define PWH 136

// ---------------- W fragment prep: all 3 layers in one launch (grid=3) ----------------
__global__ __launch_bounds__(256) void k_prepw(const float* __restrict__ W0,
                                               const float* __restrict__ W1,
                                               const float* __restrict__ W2) {
    extern __shared__ char smemraw[];
    __half* sWh = reinterpret_cast<__half*>(smemraw);     // [128][PWH]
    __half* sWl = sWh + 128 * PWH;

    const float* W = (blockIdx.x == 0) ? W0 : ((blockIdx.x == 1) ? W1 : W2);
    uint4* outh = g_wfh + blockIdx.x * 2048;
    uint4* outl = g_wfl + blockIdx.x * 2048;

    int tid = threadIdx.x;
    int lane = tid & 31;
    int wid = tid >> 5;

    for (int i = tid; i < 128 * 32; i += 256) {
        int k = i >> 5, cq = i & 31;
        float4 v = reinterpret_cast<const float4*>(W)[k * 32 + cq];
        __half2 h0 = __floats2half2_rn(v.x, v.y);
        __half2 h1 = __floats2half2_rn(v.z, v.w);
        float2 f0 = __half22float2(h0);
        float2 f1 = __half22float2(h1);
        __half2 l0 = __floats2half2_rn(v.x - f0.x, v.y - f0.y);
        __half2 l1 = __floats2half2_rn(v.z - f1.x, v.w - f1.y);
        int o = k * PWH + 4 * cq;
        *reinterpret_cast<__half2*>(&sWh[o])     = h0;
        *reinterpret_cast<__half2*>(&sWh[o + 2]) = h1;
        *reinterpret_cast<__half2*>(&sWl[o])     = l0;
        *reinterpret_cast<__half2*>(&sWl[o + 2]) = l1;
    }
    __syncthreads();

    int b_k = (lane & 7) + ((lane >> 3) & 1) * 8;
    int b_n = (lane >> 4) * 8;
    unsigned aH = smem_u32(&sWh[b_k * PWH + wid * 16 + b_n]);
    unsigned aL = smem_u32(&sWl[b_k * PWH + wid * 16 + b_n]);

    #pragma unroll
    for (int ks = 0; ks < 8; ks++) {
        unsigned h[4], l[4];
        unsigned dW = (unsigned)(ks * 16 * PWH * 2);
        ldsm_x4_t(h, aH + dW);
        ldsm_x4_t(l, aL + dW);
        outh[(ks * 8 + wid) * 32 + lane] = make_uint4(h[0], h[1], h[2], h[3]);
        outl[(ks * 8 + wid) * 32 + lane] = make_uint4(l[0], l[1], l[2], l[3]);
    }
}

// ---------------- GEMM: A fp16 (plain), W fp16 split; A via ldmatrix, B via LDG ----------------
__global__ __launch_bounds__(256, 3) void k_gemm(const float* __restrict__ X,
                                                 const float* __restrict__ a_src,
                                                 const float* __restrict__ a_dst,
                                                 int use_x, int layer) {
    extern __shared__ char smemraw[];
    __half* sAh = reinterpret_cast<__half*>(smemraw);     // [64][PAH]
    float* salpha = reinterpret_cast<float*>(sAh + 64 * PAH);  // [64][2]

    const uint4* wfh = g_wfh + layer * 2048;
    const uint4* wfl = g_wfl + layer * 2048;
    int tid = threadIdx.x;
    int lane = tid & 31;
    int wid = tid >> 5;
    int row0 = blockIdx.x * 64;

    int rg = wid & 1;
    int cg = wid >> 1;
    int wr = rg * 32;
    int nc0 = cg * 32;

    if (tid < 128) salpha[tid] = 0.f;

    if (use_x) {
        for (int i = tid; i < 64 * 32; i += 256) {
            int r = i >> 5, cq = i & 31;
            int grow = row0 + r;
            float4 v = make_float4(0.f, 0.f, 0.f, 0.f);
            if (grow < N_NODES)
                v = reinterpret_cast<const float4*>(X)[grow * 32 + cq];
            __half2 h0 = __floats2half2_rn(v.x, v.y);
            __half2 h1 = __floats2half2_rn(v.z, v.w);
            int o = r * PAH + 4 * cq;
            *reinterpret_cast<__half2*>(&sAh[o])     = h0;
            *reinterpret_cast<__half2*>(&sAh[o + 2]) = h1;
        }
    } else {
        for (int i = tid; i < 64 * 32; i += 256) {
            int r = i >> 5, cq = i & 31;
            int grow = row0 + r;
            uint2 v = make_uint2(0u, 0u);
            if (grow < N_NODES)
                v = reinterpret_cast<const uint2*>(g_acth)[grow * 32 + cq];
            *reinterpret_cast<uint2*>(&sAh[r * PAH + 4 * cq]) = v;
        }
    }
    __syncthreads();

    int qr = lane >> 2;
    int qc = lane & 3;

    int a_r = (lane & 7) + ((lane >> 3) & 1) * 8;
    int a_k = (lane >> 4) * 8;
    unsigned aAh0 = smem_u32(&sAh[(wr + a_r) * PAH + a_k]);
    unsigned aAh1 = smem_u32(&sAh[(wr + 16 + a_r) * PAH + a_k]);

    float c[2][4][4];
    #pragma unroll
    for (int f = 0; f < 2; f++)
        #pragma unroll
        for (int nt = 0; nt < 4; nt++) {
            c[f][nt][0] = 0.f; c[f][nt][1] = 0.f; c[f][nt][2] = 0.f; c[f][nt][3] = 0.f;
        }

    #pragma unroll
    for (int ks = 0; ks < 8; ks++) {
        unsigned ah[2][4];
        unsigned dA = (unsigned)(ks * 16 * 2);
        ldsm_x4(ah[0], aAh0 + dA);
        ldsm_x4(ah[1], aAh1 + dA);

        uint4 bh0 = __ldg(&wfh[(ks * 8 + 2 * cg + 0) * 32 + lane]);
        uint4 bh1 = __ldg(&wfh[(ks * 8 + 2 * cg + 1) * 32 + lane]);
        uint4 bl0 = __ldg(&wfl[(ks * 8 + 2 * cg + 0) * 32 + lane]);
        uint4 bl1 = __ldg(&wfl[(ks * 8 + 2 * cg + 1) * 32 + lane]);
        unsigned bhp[2][4] = {{bh0.x, bh0.y, bh0.z, bh0.w}, {bh1.x, bh1.y, bh1.z, bh1.w}};
        unsigned blp[2][4] = {{bl0.x, bl0.y, bl0.z, bl0.w}, {bl1.x, bl1.y, bl1.z, bl1.w}};

        #pragma unroll
        for (int nt = 0; nt < 4; nt++) {
            int p = nt >> 1;
            int ix = (nt & 1) * 2;
            unsigned b0h = bhp[p][ix], b1h = bhp[p][ix + 1];
            unsigned b0l = blp[p][ix], b1l = blp[p][ix + 1];
            #pragma unroll
            for (int f = 0; f < 2; f++) {
                mma_f16(c[f][nt], ah[f], b0h, b1h);   // A * W_hi
                mma_f16(c[f][nt], ah[f], b0l, b1l);   // A * W_lo
            }
        }
    }

    float als[4] = {0.f, 0.f, 0.f, 0.f};
    float ald[4] = {0.f, 0.f, 0.f, 0.f};
    __half2* hh2 = reinterpret_cast<__half2*>(g_hh);

    #pragma unroll
    for (int f = 0; f < 2; f++) {
        int r_lo = row0 + wr + f * 16 + qr;
        int r_hi = r_lo + 8;
        #pragma unroll
        for (int nt = 0; nt < 4; nt++) {
            int col0 = nc0 + nt * 8 + 2 * qc;
            float s0 = __ldg(&a_src[col0]), s1 = __ldg(&a_src[col0 + 1]);
            float d0 = __ldg(&a_dst[col0]), d1 = __ldg(&a_dst[col0 + 1]);
            float* cc = c[f][nt];
            als[f * 2 + 0] += cc[0] * s0 + cc[1] * s1;
            ald[f * 2 + 0] += cc[0] * d0 + cc[1] * d1;
            als[f * 2 + 1] += cc[2] * s0 + cc[3] * s1;
            ald[f * 2 + 1] += cc[2] * d0 + cc[3] * d1;
            if (r_lo < N_NODES)
                hh2[r_lo * 64 + (col0 >> 1)] = __floats2half2_rn(cc[0], cc[1]);
            if (r_hi < N_NODES)
                hh2[r_hi * 64 + (col0 >> 1)] = __floats2half2_rn(cc[2], cc[3]);
        }
    }
    #pragma unroll
    for (int j = 0; j < 4; j++) {
        als[j] += __shfl_xor_sync(0xffffffffu, als[j], 1);
        als[j] += __shfl_xor_sync(0xffffffffu, als[j], 2);
        ald[j] += __shfl_xor_sync(0xffffffffu, ald[j], 1);
        ald[j] += __shfl_xor_sync(0xffffffffu, ald[j], 2);
    }
    if (qc == 0) {
        #pragma unroll
        for (int f = 0; f < 2; f++) {
            int lr_lo = wr + f * 16 + qr;
            atomicAdd(&salpha[lr_lo * 2 + 0], als[f * 2 + 0]);
            atomicAdd(&salpha[lr_lo * 2 + 1], ald[f * 2 + 0]);
            atomicAdd(&salpha[(lr_lo + 8) * 2 + 0], als[f * 2 + 1]);
            atomicAdd(&salpha[(lr_lo + 8) * 2 + 1], ald[f * 2 + 1]);
        }
    }
    __syncthreads();
    if (tid < 64) {
        int grow = row0 + tid;
        if (grow < N_NODES) {
            g_as[grow] = salpha[tid * 2 + 0];
            g_ad[grow] = salpha[tid * 2 + 1];
        }
    }
}

// ---------------- aggregation: half-warp edge parallelism + HFMA2 ----------------
// Lanes 0-15 process even edges, lanes 16-31 odd edges; each lane covers
// dims [8j, 8j+7] via one uint4 per edge. Every warp instruction (incl. the
// MUFU exp and scalar loads) now covers 2 edges.
__global__ __launch_bounds__(256) void k_agg(const float* __restrict__ bias) {
    int w = (blockIdx.x * blockDim.x + threadIdx.x) >> 5;
    int lane = threadIdx.x & 31;
    if (w >= N_NODES) return;

    int beg = g_rowptr[w];
    int end = g_rowptr[w + 1];
    float ad = g_ad[w];

    int half = lane >> 4;    // 0: even edges, 1: odd edges
    int j = lane & 15;       // dim group [8j, 8j+7]
    const uint4* h4 = reinterpret_cast<const uint4*>(g_hh);  // 16 uint4 per row

    unsigned accA[4] = {0u, 0u, 0u, 0u};
    unsigned accB[4] = {0u, 0u, 0u, 0u};
    float sc = 0.f;

    int e = beg + half;
    #pragma unroll 1
    for (; e + 2 < end; e += 4) {   // edges e and e+2 for this half-warp
        int sA = g_col[e];
        int sB = g_col[e + 2];
        float vA = g_as[sA] + ad;
        float vB = g_as[sB] + ad;
        vA = vA > 0.f ? vA : 0.2f * vA;
        vB = vB > 0.f ? vB : 0.2f * vB;
        float wA = __expf(vA);
        float wB = __expf(vB);
        sc += wA + wB;
        __half2 whA = __floats2half2_rn(wA, wA);
        __half2 whB = __floats2half2_rn(wB, wB);
        unsigned wuA = *reinterpret_cast<unsigned*>(&whA);
        unsigned wuB = *reinterpret_cast<unsigned*>(&whB);
        uint4 rA = h4[sA * 16 + j];
        uint4 rB = h4[sB * 16 + j];
        hfma2(accA[0], rA.x, wuA);
        hfma2(accA[1], rA.y, wuA);
        hfma2(accA[2], rA.z, wuA);
        hfma2(accA[3], rA.w, wuA);
        hfma2(accB[0], rB.x, wuB);
        hfma2(accB[1], rB.y, wuB);
        hfma2(accB[2], rB.z, wuB);
        hfma2(accB[3], rB.w, wuB);
    }
    if (e < end) {
        int s = g_col[e];
        float v = g_as[s] + ad;
        v = v > 0.f ? v : 0.2f * v;
        float wt = __expf(v);
        sc += wt;
        __half2 wh = __floats2half2_rn(wt, wt);
        unsigned wu = *reinterpret_cast<unsigned*>(&wh);
        uint4 r = h4[s * 16 + j];
        hfma2(accA[0], r.x, wu);
        hfma2(accA[1], r.y, wu);
        hfma2(accA[2], r.z, wu);
        hfma2(accA[3], r.w, wu);
    }

    // merge B into A, then merge odd half into even half
    #pragma unroll
    for (int k = 0; k < 4; k++) accA[k] = hadd2u(accA[k], accB[k]);
    sc += __shfl_xor_sync(0xffffffffu, sc, 16);
    #pragma unroll
    for (int k = 0; k < 4; k++)
        accA[k] = hadd2u(accA[k], __shfl_xor_sync(0xffffffffu, accA[k], 16));

    float inv = 1.f / (sc + 1e-16f);
    const float4* bb4 = reinterpret_cast<const float4*>(bias);
    float4 b0 = bb4[2 * j];
    float4 b1 = bb4[2 * j + 1];

    float2 f0 = __half22float2(*reinterpret_cast<__half2*>(&accA[0]));
    float2 f1 = __half22float2(*reinterpret_cast<__half2*>(&accA[1]));
    float2 f2 = __half22float2(*reinterpret_cast<__half2*>(&accA[2]));
    float2 f3 = __half22float2(*reinterpret_cast<__half2*>(&accA[3]));
    float o[8];
    o[0] = f0.x * inv + b0.x;
    o[1] = f0.y * inv + b0.y;
    o[2] = f1.x * inv + b0.z;
    o[3] = f1.y * inv + b0.w;
    o[4] = f2.x * inv + b1.x;
    o[5] = f2.y * inv + b1.y;
    o[6] = f3.x * inv + b1.z;
    o[7] = f3.y * inv + b1.w;
    #pragma unroll
    for (int k = 0; k < 8; k++)
        o[k] = o[k] > 0.f ? o[k] : (__expf(o[k]) - 1.f);

    if (half == 0) {
        __half2 p0 = __floats2half2_rn(o[0], o[1]);
        __half2 p1 = __floats2half2_rn(o[2], o[3]);
        __half2 p2 = __floats2half2_rn(o[4], o[5]);
        __half2 p3 = __floats2half2_rn(o[6], o[7]);
        uint4 ov;
        ov.x = *reinterpret_cast<unsigned*>(&p0);
        ov.y = *reinterpret_cast<unsigned*>(&p1);
        ov.z = *reinterpret_cast<unsigned*>(&p2);
        ov.w = *reinterpret_cast<unsigned*>(&p3);
        reinterpret_cast<uint4*>(g_acth)[w * 16 + j] = ov;
    }
}

// ---------------- global mean pool (fp16 input) ----------------
__global__ __launch_bounds__(512) void k_pool(const int* __restrict__ batch,
                                              float* __restrict__ out) {
    int g = blockIdx.x;
    int tid = threadIdx.x;
    int sub = tid >> 7;
    int d = tid & 127;

    int lo = 0, hi = N_NODES;
    while (lo < hi) { int mid = (lo + hi) >> 1; if (batch[mid] < g) lo = mid + 1; else hi = mid; }
    int start = lo;
    lo = 0; hi = N_NODES;
    while (lo < hi) { int mid = (lo + hi) >> 1; if (batch[mid] < g + 1) lo = mid + 1; else hi = mid; }
    int stop = lo;

    float s = 0.f;
    for (int i = start + sub; i < stop; i += 4)
        s += __half2float(g_acth[i * 128 + d]);

    __shared__ float sm[4][128];
    sm[sub][d] = s;
    __syncthreads();
    if (sub == 0) {
        float tot = sm[0][d] + sm[1][d] + sm[2][d] + sm[3][d];
        int cnt = stop - start;
        out[g * 128 + d] = tot / (float)(cnt > 0 ? cnt : 1);
    }
}

// ---------------- launch ----------------
extern "C" void kernel_launch(void* const* d_in, const int* in_sizes, int n_in,
                              void* d_out, int out_size) {
    const float* x     = (const float*)d_in[0];
    const int*   ei    = (const int*)d_in[1];
    const int*   batch = (const int*)d_in[2];
    const float* W[3]   = { (const float*)d_in[3], (const float*)d_in[7],  (const float*)d_in[11] };
    const float* asr[3] = { (const float*)d_in[4], (const float*)d_in[8],  (const float*)d_in[12] };
    const float* ads[3] = { (const float*)d_in[5], (const float*)d_in[9],  (const float*)d_in[13] };
    const float* bs[3]  = { (const float*)d_in[6], (const float*)d_in[10], (const float*)d_in[14] };
    float* out = (float*)d_out;

    const int gemm_smem = (64 * PAH) * 2 + 128 * 4;            // ~17.9 KB
    const int prep_smem = (2 * 128 * PWH) * 2;                 // ~69.6 KB
    cudaFuncSetAttribute(k_gemm, cudaFuncAttributeMaxDynamicSharedMemorySize, gemm_smem);
    cudaFuncSetAttribute(k_prepw, cudaFuncAttributeMaxDynamicSharedMemorySize, prep_smem);

    void* degp = nullptr;
    cudaGetSymbolAddress(&degp, g_deg);

    const int gemm_grid = (N_NODES + 63) / 64;
    const int warp_grid = (N_NODES * 32 + 255) / 256;

    // fork: CSR build on side stream, prepw+gemm1 on main stream
    cudaStream_t s2;
    cudaStreamCreateWithFlags(&s2, cudaStreamNonBlocking);
    cudaEvent_t evF, evJ;
    cudaEventCreateWithFlags(&evF, cudaEventDisableTiming);
    cudaEventCreateWithFlags(&evJ, cudaEventDisableTiming);

    cudaEventRecord(evF, 0);
    cudaStreamWaitEvent(s2, evF, 0);

    // side stream: CSR chain
    cudaMemsetAsync(degp, 0, N_NODES * sizeof(int), s2);
    k_count<<<(N_EDGES + 255) / 256, 256, 0, s2>>>(ei);
    k_scan1<<<SCAN_BLOCKS, 1024, 0, s2>>>();
    k_scan3<<<(N_NODES + 255) / 256, 256, 0, s2>>>();
    k_fill<<<(E_TOTAL + 255) / 256, 256, 0, s2>>>(ei);
    cudaEventRecord(evJ, s2);

    // main stream: W prep (all layers) + layer-1 GEMM
    k_prepw<<<3, 256, prep_smem>>>(W[0], W[1], W[2]);
    k_gemm<<<gemm_grid, 256, gemm_smem>>>(x, asr[0], ads[0], 1, 0);

    // join: agg needs both gemm1 (main) and fill (side)
    cudaStreamWaitEvent(0, evJ, 0);
    k_agg<<<warp_grid, 256>>>(bs[0]);

    for (int l = 1; l < 3; l++) {
        k_gemm<<<gemm_grid, 256, gemm_smem>>>(x, asr[l], ads[l], 0, l);
        k_agg<<<warp_grid, 256>>>(bs[l]);
    }

    k_pool<<<N_GRAPHS, 512>>>(batch, out);
}